// round 5
// baseline (speedup 1.0000x reference)
#include <cuda_runtime.h>
#include <cuda_bf16.h>
#include <cstdint>
#include <math.h>

#define NN 8192
#define DD 512

#define BM 128
#define BN 128
#define BK 128                       // fp8 elems per chunk = 128 B per row
#define NCHUNKS (DD / BK)            // 4
#define GRID_X (NN / BN)             // 64
#define GRID_Y (NN / BM)             // 64

#define QSCALE 16.0f                 // pre-quantization scale
#define QSCALE2 256.0f               // QSCALE^2

// dynamic SMEM
#define SA 0                         // 2 x 16KB
#define SB 32768                     // 2 x 16KB
#define SRED 65536                   // 256 floats
#define SMEM_TOTAL (65536 + 1024)

__device__ uint8_t g_cn8[(size_t)NN * DD];
__device__ uint8_t g_en8[(size_t)NN * DD];
__device__ float g_prow[(size_t)GRID_X * NN];
__device__ float g_pcol[(size_t)GRID_Y * NN];
__device__ float g_diag[NN];

__device__ __forceinline__ uint32_t smem_u32(const void* p) {
    uint32_t a;
    asm("{ .reg .u64 t; cvta.to.shared.u64 t, %1; cvt.u32.u64 %0, t; }"
        : "=r"(a) : "l"(p));
    return a;
}

// ---------------- 1. normalize both inputs -> e4m3*16 (one launch) ----------
__global__ void knorm(const float* __restrict__ in0, const float* __restrict__ in1,
                      uint8_t* __restrict__ out0, uint8_t* __restrict__ out1,
                      float* __restrict__ loss_out) {
    if (blockIdx.x == 0 && threadIdx.x == 0) loss_out[0] = 0.0f;   // init accum
    int b = blockIdx.x;
    const float* in = (b < NN) ? in0 : in1;
    uint8_t* out = (b < NN) ? out0 : out1;
    int row = b & (NN - 1);
    const float4* ip = reinterpret_cast<const float4*>(in + (size_t)row * DD);
    float4 v = ip[threadIdx.x];
    float ss = v.x * v.x + v.y * v.y + v.z * v.z + v.w * v.w;
    #pragma unroll
    for (int o = 16; o; o >>= 1) ss += __shfl_xor_sync(0xffffffffu, ss, o);
    __shared__ float sm[4];
    if ((threadIdx.x & 31) == 0) sm[threadIdx.x >> 5] = ss;
    __syncthreads();
    float s = QSCALE / fmaxf(sqrtf(sm[0] + sm[1] + sm[2] + sm[3]), 1e-8f);
    uint16_t h0, h1;
    asm("cvt.rn.satfinite.e4m3x2.f32 %0, %1, %2;"
        : "=h"(h0) : "f"(v.y * s), "f"(v.x * s));
    asm("cvt.rn.satfinite.e4m3x2.f32 %0, %1, %2;"
        : "=h"(h1) : "f"(v.w * s), "f"(v.z * s));
    uint32_t w = (uint32_t)h0 | ((uint32_t)h1 << 16);
    reinterpret_cast<uint32_t*>(out + (size_t)row * DD)[threadIdx.x] = w;
}

// ---------------- 2. fused fp8 mma.sync GEMM + exp-sum epilogue -------------
// 4 warps, warp grid 2x2, warp tile 64x64; frags 4(m16) x 8(n8), k32 steps
__global__ void __launch_bounds__(128, 2) kmain(const float* __restrict__ tptr) {
    extern __shared__ char smem[];
    const uint32_t smb = smem_u32(smem);
    const int tid = threadIdx.x;
    const int wid = tid >> 5, lid = tid & 31;
    const int wm = wid >> 1, wn = wid & 1;
    const int bm = blockIdx.y * BM;
    const int bn = blockIdx.x * BN;

    float acc[4][8][4];
    #pragma unroll
    for (int i = 0; i < 4; i++)
        #pragma unroll
        for (int j = 0; j < 8; j++)
            #pragma unroll
            for (int e = 0; e < 4; e++) acc[i][j][e] = 0.0f;

    // ---- cp.async loader: A+B, 128 rows x 128B each, xor-swizzled ----
    auto load_chunk = [&](int chunk, int buf) {
        const char* asrc = (const char*)(g_cn8 + (size_t)bm * DD + chunk * BK);
        const char* bsrc = (const char*)(g_en8 + (size_t)bn * DD + chunk * BK);
        #pragma unroll
        for (int i = 0; i < 8; i++) {
            int idx = tid + i * 128;            // [0,1024)
            int r = idx >> 3, c = idx & 7;      // row, 16B group
            uint32_t soff = r * 128 + ((c ^ (r & 7)) * 16);
            uint32_t da = smb + SA + buf * 16384 + soff;
            uint32_t db = smb + SB + buf * 16384 + soff;
            const void* ga = asrc + (size_t)r * DD + c * 16;
            const void* gb = bsrc + (size_t)r * DD + c * 16;
            asm volatile("cp.async.cg.shared.global [%0], [%1], 16;" :: "r"(da), "l"(ga));
            asm volatile("cp.async.cg.shared.global [%0], [%1], 16;" :: "r"(db), "l"(gb));
        }
        asm volatile("cp.async.commit_group;" ::: "memory");
    };

    auto compute = [&](int buf) {
        const uint32_t abase = smb + SA + buf * 16384 + (wm * 64) * 128;
        const uint32_t bbase = smb + SB + buf * 16384 + (wn * 64) * 128;
        #pragma unroll
        for (int kk = 0; kk < 4; kk++) {        // 4 x k32 per 128B chunk
            const int cg = kk * 2 + (lid >> 4); // 16B group within row
            uint32_t a[4][4];
            #pragma unroll
            for (int mi = 0; mi < 4; mi++) {
                int r = mi * 16 + (lid & 15);
                uint32_t addr = abase + r * 128 + ((cg ^ (r & 7)) * 16);
                asm volatile("ldmatrix.sync.aligned.m8n8.x4.shared.b16 {%0,%1,%2,%3}, [%4];"
                             : "=r"(a[mi][0]), "=r"(a[mi][1]), "=r"(a[mi][2]), "=r"(a[mi][3])
                             : "r"(addr));
            }
            uint32_t b[4][4];
            #pragma unroll
            for (int nb = 0; nb < 4; nb++) {
                int r = nb * 16 + (lid & 15);
                uint32_t addr = bbase + r * 128 + ((cg ^ (r & 7)) * 16);
                asm volatile("ldmatrix.sync.aligned.m8n8.x4.shared.b16 {%0,%1,%2,%3}, [%4];"
                             : "=r"(b[nb][0]), "=r"(b[nb][1]), "=r"(b[nb][2]), "=r"(b[nb][3])
                             : "r"(addr));
            }
            #pragma unroll
            for (int mi = 0; mi < 4; mi++)
                #pragma unroll
                for (int nj = 0; nj < 8; nj++) {
                    const int nb = nj >> 1, hi = nj & 1;
                    asm volatile(
                        "mma.sync.aligned.m16n8k32.row.col.f32.e4m3.e4m3.f32 "
                        "{%0,%1,%2,%3}, {%4,%5,%6,%7}, {%8,%9}, {%0,%1,%2,%3};"
                        : "+f"(acc[mi][nj][0]), "+f"(acc[mi][nj][1]),
                          "+f"(acc[mi][nj][2]), "+f"(acc[mi][nj][3])
                        : "r"(a[mi][0]), "r"(a[mi][1]), "r"(a[mi][2]), "r"(a[mi][3]),
                          "r"(b[nb][hi]), "r"(b[nb][2 + hi]));
                }
        }
    };

    load_chunk(0, 0);
    #pragma unroll 1
    for (int k = 0; k < NCHUNKS; k++) {
        if (k + 1 < NCHUNKS) {
            load_chunk(k + 1, (k + 1) & 1);
            asm volatile("cp.async.wait_group 1;" ::: "memory");
        } else {
            asm volatile("cp.async.wait_group 0;" ::: "memory");
        }
        __syncthreads();
        compute(k & 1);
        __syncthreads();
    }

    // ---- epilogue: exp with fixed shift M0 = 1/T ----
    float* sm_row = (float*)(smem + SRED);
    float* sm_col = sm_row + 128;
    if (tid < 128) { sm_row[tid] = 0.0f; sm_col[tid] = 0.0f; }
    __syncthreads();

    const float invT = 1.0f / *tptr;
    const float M0 = invT;
    const float lscale = invT / QSCALE2;
    const bool hasdiag = (bm == bn);
    float rowacc[4][2] = {};
    float colacc[8][2] = {};

    #pragma unroll
    for (int mi = 0; mi < 4; mi++)
        #pragma unroll
        for (int nj = 0; nj < 8; nj++)
            #pragma unroll
            for (int e = 0; e < 4; e++) {
                const int h = e >> 1, p = e & 1;
                float logit = acc[mi][nj][e] * lscale;
                float ex = __expf(logit - M0);
                if (hasdiag) {
                    int gr = wm * 64 + mi * 16 + h * 8 + (lid >> 2);
                    int gc = wn * 64 + nj * 8 + (lid & 3) * 2 + p;
                    if (gr == gc) { g_diag[bm + gr] = logit; ex = 0.0f; }
                }
                rowacc[mi][h] += ex;
                colacc[nj][p] += ex;
            }

    #pragma unroll
    for (int mi = 0; mi < 4; mi++)
        #pragma unroll
        for (int h = 0; h < 2; h++) {
            float v = rowacc[mi][h];
            v += __shfl_xor_sync(0xffffffffu, v, 1);
            v += __shfl_xor_sync(0xffffffffu, v, 2);
            if ((lid & 3) == 0)
                atomicAdd(&sm_row[wm * 64 + mi * 16 + h * 8 + (lid >> 2)], v);
        }
    #pragma unroll
    for (int nj = 0; nj < 8; nj++)
        #pragma unroll
        for (int p = 0; p < 2; p++) {
            float v = colacc[nj][p];
            v += __shfl_xor_sync(0xffffffffu, v, 4);
            v += __shfl_xor_sync(0xffffffffu, v, 8);
            v += __shfl_xor_sync(0xffffffffu, v, 16);
            if (lid < 4)
                atomicAdd(&sm_col[wn * 64 + nj * 8 + (lid & 3) * 2 + p], v);
        }
    __syncthreads();

    g_prow[(size_t)blockIdx.x * NN + bm + tid] = sm_row[tid];
    g_pcol[(size_t)blockIdx.y * NN + bn + tid] = sm_col[tid];
}

// ---------------- 3. reduce partials -> LSE -> loss (fused) -----------------
__global__ void klse(const float* __restrict__ tptr, float* __restrict__ out) {
    const float M0 = 1.0f / *tptr;
    int i = blockIdx.x * 256 + threadIdx.x;
    float sr = 0.0f, sc = 0.0f;
    #pragma unroll 8
    for (int t = 0; t < GRID_X; t++) sr += g_prow[(size_t)t * NN + i];
    #pragma unroll 8
    for (int t = 0; t < GRID_Y; t++) sc += g_pcol[(size_t)t * NN + i];
    float v = 2.0f * M0 + __logf(sr) + __logf(sc) - 2.0f * g_diag[i];

    __shared__ float red[256];
    red[threadIdx.x] = v;
    __syncthreads();
    for (int o = 128; o; o >>= 1) {
        if (threadIdx.x < o) red[threadIdx.x] += red[threadIdx.x + o];
        __syncthreads();
    }
    if (threadIdx.x == 0) atomicAdd(out, red[0] * (1.0f / (float)NN));
}

// ---------------- launcher ---------------------------------------------------
extern "C" void kernel_launch(void* const* d_in, const int* in_sizes, int n_in,
                              void* d_out, int out_size) {
    const float* cxr  = (const float*)d_in[0];
    const float* ehr  = (const float*)d_in[1];
    const float* temp = (const float*)d_in[2];

    uint8_t *cn8, *en8;
    cudaGetSymbolAddress((void**)&cn8, g_cn8);
    cudaGetSymbolAddress((void**)&en8, g_en8);

    cudaFuncSetAttribute(kmain, cudaFuncAttributeMaxDynamicSharedMemorySize,
                         SMEM_TOTAL);

    knorm<<<2 * NN, 128>>>(cxr, ehr, cn8, en8, (float*)d_out);
    kmain<<<dim3(GRID_X, GRID_Y), 128, SMEM_TOTAL>>>(temp);
    klse<<<32, 256>>>(temp, (float*)d_out);
}